// round 1
// baseline (speedup 1.0000x reference)
#include <cuda_runtime.h>
#include <cstdint>
#include <climits>

#define B_IMG   32
#define N_PRED  25200
#define KTOP    1024
#define NBINS   4096
#define NCAND   2048
#define CONF_T  0.25f
#define IOU_T   0.45f

// ---------------- scratch (static device globals; no allocation) ----------------
__device__ float        g_scores[B_IMG * N_PRED];        // ~3.2 MB
__device__ unsigned int g_hist[B_IMG * NBINS];           // 512 KB
__device__ float4       g_boxes[B_IMG * KTOP];           // 512 KB
__device__ float        g_topsc[B_IMG * KTOP];           // 128 KB
__device__ unsigned int g_mask[B_IMG * KTOP * 32];       // 4 MB

// ---------------- K0: zero histograms ----------------
__global__ void k0_zero_hist() {
    int i = blockIdx.x * blockDim.x + threadIdx.x;
    if (i < B_IMG * NBINS) g_hist[i] = 0u;
}

// ---------------- K1: scores + histogram ----------------
__global__ void k1_score_hist(const float* __restrict__ pred) {
    int b = blockIdx.y;
    int i = blockIdx.x * blockDim.x + threadIdx.x;
    if (i >= N_PRED) return;
    const float* p = pred + ((size_t)(b * N_PRED + i)) * 16;
    float obj = p[4];
    float cls = p[15];
    float sc  = __fmul_rn(cls, obj);
    bool valid = (obj > CONF_T) && (sc > CONF_T);
    g_scores[b * N_PRED + i] = valid ? sc : -1.0f;
    if (valid) {
        unsigned bin = (__float_as_uint(sc) - 0x3E800000u) >> 12;
        if (bin > NBINS - 1) bin = NBINS - 1;
        atomicAdd(&g_hist[b * NBINS + bin], 1u);
    }
}

// ---------------- K2: threshold select + compact + bitonic sort + gather ----------------
__global__ void k2_topk(const float* __restrict__ pred, float* __restrict__ dout) {
    __shared__ unsigned int       s_cntrev[NBINS];     // reversed-bin counts (r=0 is top bin)
    __shared__ int                s_arr[1024];
    __shared__ unsigned long long s_cand[NCAND];
    __shared__ int                s_tstar, s_binB, s_cnt;

    int b   = blockIdx.x;
    int tid = threadIdx.x;

    #pragma unroll
    for (int q = 0; q < 4; q++) {
        int r = tid * 4 + q;
        s_cntrev[r] = g_hist[b * NBINS + (NBINS - 1 - r)];
    }
    if (tid == 0) { s_tstar = INT_MAX; s_cnt = 0; s_binB = 0; }
    __syncthreads();

    int v = (int)(s_cntrev[tid*4] + s_cntrev[tid*4+1] + s_cntrev[tid*4+2] + s_cntrev[tid*4+3]);
    s_arr[tid] = v;
    // Hillis-Steele inclusive scan over 1024 per-thread partials
    for (int off = 1; off < 1024; off <<= 1) {
        __syncthreads();
        int a = (tid >= off) ? s_arr[tid - off] : 0;
        __syncthreads();
        s_arr[tid] += a;
    }
    __syncthreads();
    int incl = s_arr[tid];
    int excl = (tid > 0) ? s_arr[tid - 1] : 0;
    if (incl >= KTOP && excl < KTOP) atomicMin(&s_tstar, tid);
    __syncthreads();
    if (tid == s_tstar) {
        int c = excl;
        int rstar = tid * 4 + 3;
        #pragma unroll
        for (int q = 0; q < 4; q++) {
            c += (int)s_cntrev[tid * 4 + q];
            if (c >= KTOP) { rstar = tid * 4 + q; break; }
        }
        s_binB = (NBINS - 1) - rstar;
    }
    __syncthreads();
    int binB = s_binB;   // 0 if total valid < KTOP (take all valid)

    // Compact candidates with 64-bit keys: (~monotonic(score) << 32) | index
    // ascending sort => score-descending, stable by index (matches lax.top_k)
    for (int i = tid; i < N_PRED; i += 1024) {
        float sc = g_scores[b * N_PRED + i];
        if (sc > 0.0f) {
            unsigned bits = __float_as_uint(sc);
            unsigned bin  = (bits - 0x3E800000u) >> 12;
            if (bin > NBINS - 1) bin = NBINS - 1;
            if ((int)bin >= binB) {
                unsigned desc = ~(bits | 0x80000000u);
                unsigned long long key = ((unsigned long long)desc << 32) | (unsigned)i;
                int pos = atomicAdd(&s_cnt, 1);
                if (pos < NCAND) s_cand[pos] = key;
            }
        }
    }
    __syncthreads();
    int cnt = s_cnt; if (cnt > NCAND) cnt = NCAND;
    // PAD decodes to score = -1.0f (so vmask=false, keep=false, row zeroed)
    const unsigned long long PAD = ((unsigned long long)0xBF800000u << 32);
    for (int i0 = tid; i0 < NCAND; i0 += 1024)
        if (i0 >= cnt) s_cand[i0] = PAD;

    // bitonic sort (ascending), 2048 elems, 1024 threads
    for (int k = 2; k <= NCAND; k <<= 1) {
        for (int j = k >> 1; j > 0; j >>= 1) {
            __syncthreads();
            #pragma unroll
            for (int rep = 0; rep < 2; rep++) {
                int i0 = tid + rep * 1024;
                int ixj = i0 ^ j;
                if (ixj > i0) {
                    unsigned long long a = s_cand[i0], c = s_cand[ixj];
                    bool up = ((i0 & k) == 0);
                    if (up ? (a > c) : (a < c)) { s_cand[i0] = c; s_cand[ixj] = a; }
                }
            }
        }
    }
    __syncthreads();

    // gather top-1024 rows, compute boxes, write unmasked det + scratch
    unsigned long long key = s_cand[tid];
    unsigned idx  = (unsigned)(key & 0xFFFFFFFFu);
    unsigned mono = ~((unsigned)(key >> 32));
    unsigned sbits = (mono & 0x80000000u) ? (mono & 0x7FFFFFFFu) : ~mono;
    float sc = __uint_as_float(sbits);

    const float* p = pred + ((size_t)(b * N_PRED) + idx) * 16;
    float cx = p[0], cy = p[1], w = p[2], h = p[3];
    float hw = __fmul_rn(w, 0.5f), hh = __fmul_rn(h, 0.5f);
    float x1 = __fsub_rn(cx, hw), y1 = __fsub_rn(cy, hh);
    float x2 = __fadd_rn(cx, hw), y2 = __fadd_rn(cy, hh);

    float* o = dout + ((size_t)(b * KTOP) + tid) * 16;
    o[0] = x1; o[1] = y1; o[2] = x2; o[3] = y2; o[4] = sc;
    #pragma unroll
    for (int c2 = 0; c2 < 10; c2++) o[5 + c2] = p[5 + c2];
    o[15] = 0.0f;

    g_boxes[b * KTOP + tid] = make_float4(x1, y1, x2, y2);
    g_topsc[b * KTOP + tid] = sc;
}

// ---------------- K3: suppression bitmask (j > i, iou > thr) ----------------
__global__ void k3_mask() {
    __shared__ float4 sbox[KTOP];
    __shared__ float  sarea[KTOP];
    int b = blockIdx.y;
    int t = threadIdx.x;

    float4 bx = g_boxes[b * KTOP + t];
    sbox[t]  = bx;
    sarea[t] = __fmul_rn(__fsub_rn(bx.z, bx.x), __fsub_rn(bx.w, bx.y));
    __syncthreads();

    int lane = t & 31;
    int w    = t >> 5;                 // word index: uniform per warp -> broadcast smem loads
    int i    = blockIdx.x * 32 + lane; // row: per-lane
    unsigned bits = 0;

    if (w * 32 + 31 > i) {             // whole warp skips lower-triangle words
        float4 bi = sbox[i];
        float  ai = sarea[i];
        #pragma unroll
        for (int kk = 0; kk < 32; kk++) {
            int j = w * 32 + kk;
            float4 bj = sbox[j];
            float ltx = fmaxf(bi.x, bj.x), lty = fmaxf(bi.y, bj.y);
            float rbx = fminf(bi.z, bj.z), rby = fminf(bi.w, bj.w);
            float iw = fmaxf(__fsub_rn(rbx, ltx), 0.0f);
            float ih = fmaxf(__fsub_rn(rby, lty), 0.0f);
            float inter = __fmul_rn(iw, ih);
            float den = __fadd_rn(__fsub_rn(__fadd_rn(ai, sarea[j]), inter), 1e-7f);
            float iou = __fdiv_rn(inter, den);
            if (j > i && iou > IOU_T) bits |= (1u << kk);
        }
    }
    g_mask[((size_t)b * KTOP + i) * 32 + w] = bits;
}

// ---------------- K4: sequential greedy reduce + masked output ----------------
__global__ void k4_reduce(float* __restrict__ dout, float* __restrict__ keepout, int writeKeep) {
    extern __shared__ unsigned int smask[];   // KTOP * 33 (padded: conflict-free column loads)
    __shared__ unsigned int s_vm[32];
    __shared__ unsigned int s_keep[32];

    int b   = blockIdx.x;
    int tid = threadIdx.x;

    const unsigned int* gm = &g_mask[(size_t)b * KTOP * 32];
    for (int idx = tid; idx < KTOP * 32; idx += 1024) {
        int i = idx >> 5, l = idx & 31;
        smask[i * 33 + l] = gm[idx];
    }
    float sc = g_topsc[b * KTOP + tid];
    unsigned bal = __ballot_sync(0xFFFFFFFFu, sc > 0.0f);
    if ((tid & 31) == 0) s_vm[tid >> 5] = bal;
    __syncthreads();

    if (tid < 32) {
        int l = tid;
        unsigned removed = ~s_vm[l];          // keep = vmask initially
        unsigned m = smask[l];                // prefetch row 0
        for (int i = 0; i < KTOP; i++) {
            unsigned rw = __shfl_sync(0xFFFFFFFFu, removed, i >> 5);
            unsigned mn = (i < KTOP - 1) ? smask[(i + 1) * 33 + l] : 0u;  // off-chain prefetch
            if (!((rw >> (i & 31)) & 1u)) removed |= m;
            m = mn;
        }
        s_keep[l] = ~removed;
    }
    __syncthreads();

    unsigned keepbit = (s_keep[tid >> 5] >> (tid & 31)) & 1u;
    float* o = dout + ((size_t)b * KTOP + tid) * 16;
    if (!keepbit) {
        float4 z = make_float4(0.f, 0.f, 0.f, 0.f);
        ((float4*)o)[0] = z; ((float4*)o)[1] = z;
        ((float4*)o)[2] = z; ((float4*)o)[3] = z;
    }
    if (writeKeep) keepout[b * KTOP + tid] = keepbit ? 1.0f : 0.0f;
}

// ---------------- launch ----------------
extern "C" void kernel_launch(void* const* d_in, const int* in_sizes, int n_in,
                              void* d_out, int out_size) {
    const float* pred = (const float*)d_in[0];
    float* out = (float*)d_out;
    const int DET = B_IMG * KTOP * 16;
    int writeKeep = (out_size >= DET + B_IMG * KTOP) ? 1 : 0;
    float* keepout = out + DET;

    k0_zero_hist<<<(B_IMG * NBINS + 1023) / 1024, 1024>>>();
    k1_score_hist<<<dim3((N_PRED + 1023) / 1024, B_IMG), 1024>>>(pred);
    k2_topk<<<B_IMG, 1024>>>(pred, out);
    k3_mask<<<dim3(32, B_IMG), 1024>>>();

    cudaFuncSetAttribute((const void*)k4_reduce,
                         cudaFuncAttributeMaxDynamicSharedMemorySize, KTOP * 33 * 4);
    k4_reduce<<<B_IMG, 1024, KTOP * 33 * 4>>>(out, keepout, writeKeep);
}

// round 2
// speedup vs baseline: 1.3479x; 1.3479x over previous
#include <cuda_runtime.h>
#include <cstdint>
#include <climits>

#define B_IMG   32
#define N_PRED  25200
#define KTOP    1024
#define NBINS   4096
#define NCAND   2048
#define CONF_T  0.25f
#define IOU_T   0.45f
#define NTRI    528   // 32*33/2 upper-triangle 32x32 word-blocks

// ---------------- scratch (static device globals; no allocation) ----------------
__device__ float        g_scores[B_IMG * N_PRED];
__device__ unsigned int g_hist[B_IMG * NBINS];
__device__ float4       g_boxes[B_IMG * KTOP];
__device__ float        g_topsc[B_IMG * KTOP];
__device__ unsigned int g_mask[B_IMG * 32 * KTOP];   // [b][word w][row i]
__device__ unsigned int g_diag[B_IMG * 32 * 32];     // [b][blk][lane] diagonal words
__device__ unsigned int g_keepw[B_IMG * 32];

// ---------------- K0: zero histograms ----------------
__global__ void k0_zero_hist() {
    int i = blockIdx.x * blockDim.x + threadIdx.x;
    if (i < B_IMG * NBINS) g_hist[i] = 0u;
}

// ---------------- K1: scores + histogram ----------------
__global__ void k1_score_hist(const float* __restrict__ pred) {
    int b = blockIdx.y;
    int i = blockIdx.x * blockDim.x + threadIdx.x;
    if (i >= N_PRED) return;
    const float* p = pred + ((size_t)(b * N_PRED + i)) * 16;
    float obj = p[4];
    float cls = p[15];
    float sc  = __fmul_rn(cls, obj);
    bool valid = (obj > CONF_T) && (sc > CONF_T);
    g_scores[b * N_PRED + i] = valid ? sc : -1.0f;
    if (valid) {
        unsigned bin = (__float_as_uint(sc) - 0x3E800000u) >> 12;
        if (bin > NBINS - 1) bin = NBINS - 1;
        atomicAdd(&g_hist[b * NBINS + bin], 1u);
    }
}

// ---------------- K2: threshold select + compact + bitonic sort + gather ----------------
__global__ void k2_topk(const float* __restrict__ pred, float* __restrict__ dout) {
    __shared__ unsigned int       s_cntrev[NBINS];
    __shared__ int                s_arr[1024];
    __shared__ unsigned long long s_cand[NCAND];
    __shared__ int                s_tstar, s_binB, s_cnt;

    int b   = blockIdx.x;
    int tid = threadIdx.x;

    #pragma unroll
    for (int q = 0; q < 4; q++) {
        int r = tid * 4 + q;
        s_cntrev[r] = g_hist[b * NBINS + (NBINS - 1 - r)];
    }
    if (tid == 0) { s_tstar = INT_MAX; s_cnt = 0; s_binB = 0; }
    __syncthreads();

    int v = (int)(s_cntrev[tid*4] + s_cntrev[tid*4+1] + s_cntrev[tid*4+2] + s_cntrev[tid*4+3]);
    s_arr[tid] = v;
    for (int off = 1; off < 1024; off <<= 1) {
        __syncthreads();
        int a = (tid >= off) ? s_arr[tid - off] : 0;
        __syncthreads();
        s_arr[tid] += a;
    }
    __syncthreads();
    int incl = s_arr[tid];
    int excl = (tid > 0) ? s_arr[tid - 1] : 0;
    if (incl >= KTOP && excl < KTOP) atomicMin(&s_tstar, tid);
    __syncthreads();
    if (tid == s_tstar) {
        int c = excl;
        int rstar = tid * 4 + 3;
        #pragma unroll
        for (int q = 0; q < 4; q++) {
            c += (int)s_cntrev[tid * 4 + q];
            if (c >= KTOP) { rstar = tid * 4 + q; break; }
        }
        s_binB = (NBINS - 1) - rstar;
    }
    __syncthreads();
    int binB = s_binB;

    for (int i = tid; i < N_PRED; i += 1024) {
        float sc = g_scores[b * N_PRED + i];
        if (sc > 0.0f) {
            unsigned bits = __float_as_uint(sc);
            unsigned bin  = (bits - 0x3E800000u) >> 12;
            if (bin > NBINS - 1) bin = NBINS - 1;
            if ((int)bin >= binB) {
                unsigned desc = ~(bits | 0x80000000u);
                unsigned long long key = ((unsigned long long)desc << 32) | (unsigned)i;
                int pos = atomicAdd(&s_cnt, 1);
                if (pos < NCAND) s_cand[pos] = key;
            }
        }
    }
    __syncthreads();
    int cnt = s_cnt; if (cnt > NCAND) cnt = NCAND;
    const unsigned long long PAD = ((unsigned long long)0xBF800000u << 32);
    for (int i0 = tid; i0 < NCAND; i0 += 1024)
        if (i0 >= cnt) s_cand[i0] = PAD;

    for (int k = 2; k <= NCAND; k <<= 1) {
        for (int j = k >> 1; j > 0; j >>= 1) {
            __syncthreads();
            #pragma unroll
            for (int rep = 0; rep < 2; rep++) {
                int i0 = tid + rep * 1024;
                int ixj = i0 ^ j;
                if (ixj > i0) {
                    unsigned long long a = s_cand[i0], c = s_cand[ixj];
                    bool up = ((i0 & k) == 0);
                    if (up ? (a > c) : (a < c)) { s_cand[i0] = c; s_cand[ixj] = a; }
                }
            }
        }
    }
    __syncthreads();

    unsigned long long key = s_cand[tid];
    unsigned idx  = (unsigned)(key & 0xFFFFFFFFu);
    unsigned mono = ~((unsigned)(key >> 32));
    unsigned sbits = (mono & 0x80000000u) ? (mono & 0x7FFFFFFFu) : ~mono;
    float sc = __uint_as_float(sbits);

    const float4* p4 = (const float4*)(pred + (((size_t)(b * N_PRED)) + idx) * 16);
    float4 v0 = p4[0];   // cx, cy, w, h
    float4 v1 = p4[1];   // obj, p5, p6, p7
    float4 v2 = p4[2];   // p8..p11
    float4 v3 = p4[3];   // p12, p13, p14, cls

    float hw = __fmul_rn(v0.z, 0.5f), hh = __fmul_rn(v0.w, 0.5f);
    float x1 = __fsub_rn(v0.x, hw), y1 = __fsub_rn(v0.y, hh);
    float x2 = __fadd_rn(v0.x, hw), y2 = __fadd_rn(v0.y, hh);

    float4* o4 = (float4*)(dout + (((size_t)(b * KTOP)) + tid) * 16);
    o4[0] = make_float4(x1, y1, x2, y2);
    o4[1] = make_float4(sc, v1.y, v1.z, v1.w);
    o4[2] = v2;
    o4[3] = make_float4(v3.x, v3.y, v3.z, 0.0f);

    g_boxes[b * KTOP + tid] = make_float4(x1, y1, x2, y2);
    g_topsc[b * KTOP + tid] = sc;
}

// ---------------- K3: suppression bitmask, triangle-packed, div-free ----------------
__global__ void k3_mask() {
    __shared__ float4 sbox[KTOP];
    __shared__ float  sarea[KTOP];
    int b = blockIdx.y;
    int t = threadIdx.x;

    float4 bx = g_boxes[b * KTOP + t];
    sbox[t]  = bx;
    sarea[t] = __fmul_rn(__fsub_rn(bx.z, bx.x), __fsub_rn(bx.w, bx.y));
    __syncthreads();

    int g = blockIdx.x * 32 + (t >> 5);        // warp-item id 0..543
    if (g >= NTRI) return;

    // map g -> (rowblock r, wordblock w>=r) in the upper triangle
    int u = NTRI - g;                           // 1..528
    int n = (int)((__fsqrt_rn((float)(8 * u + 1)) - 1.0f) * 0.5f);
    while (n * (n + 1) / 2 < u) n++;
    while ((n - 1) * n / 2 >= u) n--;
    int r    = 32 - n;
    int base = NTRI - n * (n + 1) / 2;
    int w    = r + (g - base);

    int lane = t & 31;
    int i = r * 32 + lane;
    float4 bi = sbox[i];
    float  ai = sarea[i];

    unsigned sup = 0, ambw = 0;
    #pragma unroll
    for (int kk = 0; kk < 32; kk++) {
        int j = w * 32 + kk;
        float4 bj = sbox[j];
        float  aj = sarea[j];
        float iw = fmaxf(__fsub_rn(fminf(bi.z, bj.z), fmaxf(bi.x, bj.x)), 0.0f);
        float ih = fmaxf(__fsub_rn(fminf(bi.w, bj.w), fmaxf(bi.y, bj.y)), 0.0f);
        float inter = __fmul_rn(iw, ih);
        float den = __fadd_rn(__fsub_rn(__fadd_rn(ai, aj), inter), 1e-7f);
        if (inter > __fmul_rn(den, 0.45000076f)) sup  |= 1u << kk;
        if (inter > __fmul_rn(den, 0.44999924f)) ambw |= 1u << kk;
    }
    ambw &= ~sup;
    if (w == r) {                // strict upper triangle within diagonal block
        unsigned m = 0xFFFFFFFEu << lane;
        sup &= m; ambw &= m;
    }
    // rare exact resolution (bit-exact vs reference's RN divide)
    while (ambw) {
        int kk = __ffs(ambw) - 1; ambw &= ambw - 1;
        int j = w * 32 + kk;
        float4 bj = sbox[j];
        float  aj = sarea[j];
        float iw = fmaxf(__fsub_rn(fminf(bi.z, bj.z), fmaxf(bi.x, bj.x)), 0.0f);
        float ih = fmaxf(__fsub_rn(fminf(bi.w, bj.w), fmaxf(bi.y, bj.y)), 0.0f);
        float inter = __fmul_rn(iw, ih);
        float den = __fadd_rn(__fsub_rn(__fadd_rn(ai, aj), inter), 1e-7f);
        if (__fdiv_rn(inter, den) > IOU_T) sup |= 1u << kk;
    }
    g_mask[((size_t)b * 32 + w) * KTOP + i] = sup;       // coalesced over lanes
    if (w == r) g_diag[(b * 32 + r) * 32 + lane] = sup;
}

// ---------------- K4a: block-serial greedy reduce (32 imgs x 1 warp) ----------------
__global__ void k4a_serial() {
    int b = blockIdx.x;
    int l = threadIdx.x;   // 32 threads

    // build vmask words: vm(lane l) = valid bits of rows l*32..l*32+31
    unsigned vm = 0;
    #pragma unroll
    for (int kk = 0; kk < 32; kk++) {
        float sc = g_topsc[b * KTOP + kk * 32 + l];
        unsigned wball = __ballot_sync(0xFFFFFFFFu, sc > 0.0f);
        if (l == kk) vm = wball;
    }
    unsigned removed = ~vm;

    const unsigned* gm = &g_mask[(size_t)b * 32 * KTOP];  // [w][i]
    unsigned d = g_diag[(b * 32 + 0) * 32 + l];

    for (int bi = 0; bi < 32; bi++) {
        // prefetch this block's cross words (lane l: rows bi*32..+31, word l) — contiguous
        const uint4* mrow = (const uint4*)&gm[(size_t)l * KTOP + bi * 32];
        uint4 m0 = mrow[0], m1 = mrow[1], m2 = mrow[2], m3 = mrow[3];
        uint4 m4 = mrow[4], m5 = mrow[5], m6 = mrow[6], m7 = mrow[7];
        unsigned dn = (bi < 31) ? g_diag[(b * 32 + bi + 1) * 32 + l] : 0u;

        unsigned r = __shfl_sync(0xFFFFFFFFu, removed, bi);
        unsigned dk[32];
        #pragma unroll
        for (int k = 0; k < 32; k++) dk[k] = __shfl_sync(0xFFFFFFFFu, d, k);

        // serial greedy within block: 3-op branchless chain per row
        #pragma unroll
        for (int k = 0; k < 32; k++) {
            unsigned msk = ((r >> k) & 1u) - 1u;   // ~0 if row k kept
            r |= dk[k] & msk;
        }
        unsigned keepw = ~r;

        unsigned mv[32] = { m0.x, m0.y, m0.z, m0.w, m1.x, m1.y, m1.z, m1.w,
                            m2.x, m2.y, m2.z, m2.w, m3.x, m3.y, m3.z, m3.w,
                            m4.x, m4.y, m4.z, m4.w, m5.x, m5.y, m5.z, m5.w,
                            m6.x, m6.y, m6.z, m6.w, m7.x, m7.y, m7.z, m7.w };
        unsigned acc = 0;
        #pragma unroll
        for (int k = 0; k < 32; k++) {
            unsigned msk = 0u - ((keepw >> k) & 1u);
            acc |= mv[k] & msk;
        }
        removed |= acc;
        d = dn;
    }
    g_keepw[b * 32 + l] = ~removed;
}

// ---------------- K4b: masked output ----------------
__global__ void k4b_output(float* __restrict__ dout, float* __restrict__ keepout, int writeKeep) {
    int b   = blockIdx.x;
    int tid = threadIdx.x;
    unsigned keepbit = (g_keepw[b * 32 + (tid >> 5)] >> (tid & 31)) & 1u;
    float* o = dout + ((size_t)b * KTOP + tid) * 16;
    if (!keepbit) {
        float4 z = make_float4(0.f, 0.f, 0.f, 0.f);
        ((float4*)o)[0] = z; ((float4*)o)[1] = z;
        ((float4*)o)[2] = z; ((float4*)o)[3] = z;
    }
    if (writeKeep) keepout[b * KTOP + tid] = keepbit ? 1.0f : 0.0f;
}

// ---------------- launch ----------------
extern "C" void kernel_launch(void* const* d_in, const int* in_sizes, int n_in,
                              void* d_out, int out_size) {
    const float* pred = (const float*)d_in[0];
    float* out = (float*)d_out;
    const int DET = B_IMG * KTOP * 16;
    int writeKeep = (out_size >= DET + B_IMG * KTOP) ? 1 : 0;
    float* keepout = out + DET;

    k0_zero_hist<<<(B_IMG * NBINS + 1023) / 1024, 1024>>>();
    k1_score_hist<<<dim3((N_PRED + 1023) / 1024, B_IMG), 1024>>>(pred);
    k2_topk<<<B_IMG, 1024>>>(pred, out);
    k3_mask<<<dim3(17, B_IMG), 1024>>>();
    k4a_serial<<<B_IMG, 32>>>();
    k4b_output<<<B_IMG, 1024>>>(out, keepout, writeKeep);
}

// round 4
// speedup vs baseline: 1.7691x; 1.3125x over previous
#include <cuda_runtime.h>
#include <cstdint>
#include <climits>

#define B_IMG   32
#define N_PRED  25200
#define KTOP    1024
#define NBINS   4096
#define NCAND   2048
#define CONF_T  0.25f
#define IOU_T   0.45f
#define NTRI    528   // 32*33/2 upper-triangle 32x32 word-blocks

typedef unsigned long long ull;

// ---------------- scratch (static device globals; no allocation) ----------------
__device__ float4       g_boxes[B_IMG * KTOP];
__device__ float        g_topsc[B_IMG * KTOP];
__device__ unsigned int g_mask[B_IMG * 32 * KTOP];   // [b][word w][row i]
__device__ unsigned int g_diag[B_IMG * 32 * 32];     // [b][blk][lane]

// smem layout for k12
#define SM_SCORES_BYTES (N_PRED * 4)                  // 100800
#define SM_HIST_BYTES   (NBINS * 4)                   // 16384
#define SM_CAND_BYTES   (NCAND * 8)                   // 16384
#define SM_TOTAL        (SM_SCORES_BYTES + SM_HIST_BYTES + SM_CAND_BYTES)

__device__ __forceinline__ ull umin64(ull a, ull b) { return a < b ? a : b; }
__device__ __forceinline__ ull umax64(ull a, ull b) { return a > b ? a : b; }

// ================= K12: score + hist + select + compact + sort + gather =================
__global__ void __launch_bounds__(1024, 1)
k12_topk(const float* __restrict__ pred, float* __restrict__ dout) {
    extern __shared__ unsigned char sraw[];
    float*    s_scores = (float*)sraw;
    unsigned* s_hist   = (unsigned*)(sraw + SM_SCORES_BYTES);
    ull*      s_cand   = (ull*)(sraw + SM_SCORES_BYTES + SM_HIST_BYTES);
    __shared__ int s_part[32];
    __shared__ int s_binB, s_cnt;

    int b   = blockIdx.x;
    int t   = threadIdx.x;
    int lane = t & 31, wid = t >> 5;

    #pragma unroll
    for (int r = t; r < NBINS; r += 1024) s_hist[r] = 0u;
    if (t == 0) { s_binB = 0; s_cnt = 0; }
    __syncthreads();

    // ---- scores + smem histogram ----
    const float* pb = pred + (size_t)b * N_PRED * 16;
    for (int i = t; i < N_PRED; i += 1024) {
        float obj = __ldg(pb + (size_t)i * 16 + 4);
        float cls = __ldg(pb + (size_t)i * 16 + 15);
        float sc  = __fmul_rn(cls, obj);
        bool valid = (obj > CONF_T) && (sc > CONF_T);
        s_scores[i] = valid ? sc : -1.0f;
        if (valid) {
            unsigned bin = (__float_as_uint(sc) - 0x3E800000u) >> 12;
            if (bin > NBINS - 1) bin = NBINS - 1;
            atomicAdd(&s_hist[bin], 1u);
        }
    }
    __syncthreads();

    // ---- reversed scan (warp hierarchy) + threshold bin ----
    unsigned c0 = s_hist[NBINS - 1 - 4 * t];
    unsigned c1 = s_hist[NBINS - 1 - (4 * t + 1)];
    unsigned c2 = s_hist[NBINS - 1 - (4 * t + 2)];
    unsigned c3 = s_hist[NBINS - 1 - (4 * t + 3)];
    int v = (int)(c0 + c1 + c2 + c3);
    int x = v;
    #pragma unroll
    for (int off = 1; off < 32; off <<= 1) {
        int y = __shfl_up_sync(0xFFFFFFFFu, x, off);
        if (lane >= off) x += y;
    }
    if (lane == 31) s_part[wid] = x;
    __syncthreads();
    if (wid == 0) {
        int y = s_part[lane];
        #pragma unroll
        for (int off = 1; off < 32; off <<= 1) {
            int z = __shfl_up_sync(0xFFFFFFFFu, y, off);
            if (lane >= off) y += z;
        }
        s_part[lane] = y;
    }
    __syncthreads();
    int incl = x + (wid > 0 ? s_part[wid - 1] : 0);
    int excl = incl - v;
    if (incl >= KTOP && excl < KTOP) {
        int c = excl;
        unsigned cs[4] = { c0, c1, c2, c3 };
        int rstar = 4 * t + 3;
        #pragma unroll
        for (int q = 0; q < 4; q++) {
            c += (int)cs[q];
            if (c >= KTOP) { rstar = 4 * t + q; break; }
        }
        s_binB = (NBINS - 1) - rstar;
    }
    __syncthreads();
    int binB = s_binB;

    // ---- compact candidates ----
    for (int i = t; i < N_PRED; i += 1024) {
        float sc = s_scores[i];
        if (sc > 0.0f) {
            unsigned bits = __float_as_uint(sc);
            unsigned bin  = (bits - 0x3E800000u) >> 12;
            if (bin > NBINS - 1) bin = NBINS - 1;
            if ((int)bin >= binB) {
                unsigned desc = ~(bits | 0x80000000u);
                ull key = ((ull)desc << 32) | (unsigned)i;
                int pos = atomicAdd(&s_cnt, 1);
                if (pos < NCAND) s_cand[pos] = key;
            }
        }
    }
    __syncthreads();
    int cnt = s_cnt; if (cnt > NCAND) cnt = NCAND;
    const ull PAD = ((ull)0xBF800000u << 32);
    for (int i0 = t; i0 < NCAND; i0 += 1024)
        if (i0 >= cnt) s_cand[i0] = PAD;
    __syncthreads();

    // ---- bitonic sort: registers + shfl; smem only for 32<=j<=512 ----
    ull e0 = s_cand[t];
    ull e1 = s_cand[t + 1024];
    for (int k = 2; k <= NCAND; k <<= 1) {
        bool dir0 = ((t & k) == 0);
        bool dir1 = (((t + 1024) & k) == 0);
        for (int j = k >> 1; j > 0; j >>= 1) {
            if (j == 1024) {
                ull lo = umin64(e0, e1), hi = umax64(e0, e1);
                e0 = lo; e1 = hi;
            } else if (j >= 32) {
                s_cand[t] = e0; s_cand[t + 1024] = e1;
                __syncthreads();
                ull f0 = s_cand[t ^ j];
                ull f1 = s_cand[(t ^ j) + 1024];
                bool lower = ((t & j) == 0);
                e0 = (lower == dir0) ? umin64(e0, f0) : umax64(e0, f0);
                e1 = (lower == dir1) ? umin64(e1, f1) : umax64(e1, f1);
                __syncthreads();
            } else {
                ull f0 = __shfl_xor_sync(0xFFFFFFFFu, e0, j);
                ull f1 = __shfl_xor_sync(0xFFFFFFFFu, e1, j);
                bool lower = ((t & j) == 0);
                e0 = (lower == dir0) ? umin64(e0, f0) : umax64(e0, f0);
                e1 = (lower == dir1) ? umin64(e1, f1) : umax64(e1, f1);
            }
        }
    }

    // ---- gather top-1024 (thread t holds sorted element t in e0) ----
    unsigned idx  = (unsigned)(e0 & 0xFFFFFFFFu);
    unsigned mono = ~((unsigned)(e0 >> 32));
    unsigned sbits = (mono & 0x80000000u) ? (mono & 0x7FFFFFFFu) : ~mono;
    float sc = __uint_as_float(sbits);

    const float4* p4 = (const float4*)(pb + (size_t)idx * 16);
    float4 v0 = p4[0];
    float4 v1 = p4[1];
    float4 v2 = p4[2];
    float4 v3 = p4[3];

    float hw = __fmul_rn(v0.z, 0.5f), hh = __fmul_rn(v0.w, 0.5f);
    float x1 = __fsub_rn(v0.x, hw), y1 = __fsub_rn(v0.y, hh);
    float x2 = __fadd_rn(v0.x, hw), y2 = __fadd_rn(v0.y, hh);

    float4* o4 = (float4*)(dout + (((size_t)(b * KTOP)) + t) * 16);
    o4[0] = make_float4(x1, y1, x2, y2);
    o4[1] = make_float4(sc, v1.y, v1.z, v1.w);
    o4[2] = v2;
    o4[3] = make_float4(v3.x, v3.y, v3.z, 0.0f);

    g_boxes[b * KTOP + t] = make_float4(x1, y1, x2, y2);
    g_topsc[b * KTOP + t] = sc;
}

// ================= K3: suppression bitmask, triangle-packed, FFMA screen =================
__global__ void __launch_bounds__(1024)
k3_mask() {
    __shared__ float4 sbox[KTOP];
    __shared__ float  staj[KTOP];   // 0.45 * area * (1 - 1e-5)
    int b = blockIdx.y;
    int t = threadIdx.x;

    float4 bx = g_boxes[b * KTOP + t];
    sbox[t] = bx;
    float area = __fmul_rn(__fsub_rn(bx.z, bx.x), __fsub_rn(bx.w, bx.y));
    staj[t] = 0.45f * area * 0.99999f;
    __syncthreads();

    int g = blockIdx.x * 32 + (t >> 5);
    if (g >= NTRI) return;

    // map g -> (rowblock r, wordblock w>=r)
    int u = NTRI - g;
    int n = (int)((__fsqrt_rn((float)(8 * u + 1)) - 1.0f) * 0.5f);
    while (n * (n + 1) / 2 < u) n++;
    while ((n - 1) * n / 2 >= u) n--;
    int r    = 32 - n;
    int base = NTRI - n * (n + 1) / 2;
    int w    = r + (g - base);

    int lane = t & 31;
    int i = r * 32 + lane;
    float4 bi = sbox[i];
    float  ai = __fmul_rn(__fsub_rn(bi.z, bi.x), __fsub_rn(bi.w, bi.y));
    float  tqi_lo = 0.45f * (__fadd_rn(ai, 1e-7f)) * 0.99999f;

    unsigned amb = 0;
    #pragma unroll
    for (int kk = 0; kk < 32; kk++) {
        int j = w * 32 + kk;
        float4 bj = sbox[j];
        float iw = fmaxf(__fsub_rn(fminf(bi.z, bj.z), fmaxf(bi.x, bj.x)), 0.0f);
        float ih = fmaxf(__fsub_rn(fminf(bi.w, bj.w), fmaxf(bi.y, bj.y)), 0.0f);
        float inter = __fmul_rn(iw, ih);
        // screen: 1.45*inter > 0.45*(ai+aj+eps), RHS shrunk by 1e-5 (superset of true cond)
        if (fmaf(inter, 1.45f, -tqi_lo) > staj[j]) amb |= 1u << kk;
    }
    if (w == r) amb &= (0xFFFFFFFEu << lane);   // strict upper triangle on diagonal

    // exact resolution (bit-exact vs reference's RN divide)
    unsigned sup = 0;
    while (amb) {
        int kk = __ffs(amb) - 1; amb &= amb - 1;
        int j = w * 32 + kk;
        float4 bj = sbox[j];
        float aj = __fmul_rn(__fsub_rn(bj.z, bj.x), __fsub_rn(bj.w, bj.y));
        float iw = fmaxf(__fsub_rn(fminf(bi.z, bj.z), fmaxf(bi.x, bj.x)), 0.0f);
        float ih = fmaxf(__fsub_rn(fminf(bi.w, bj.w), fmaxf(bi.y, bj.y)), 0.0f);
        float inter = __fmul_rn(iw, ih);
        float den = __fadd_rn(__fsub_rn(__fadd_rn(ai, aj), inter), 1e-7f);
        if (__fdiv_rn(inter, den) > IOU_T) sup |= 1u << kk;
    }
    g_mask[((size_t)b * 32 + w) * KTOP + i] = sup;
    if (w == r) g_diag[(b * 32 + r) * 32 + lane] = sup;
}

// ================= K4: serial greedy (warp 0 of 128-thread block) + masked output =================
__global__ void __launch_bounds__(128)
k4_reduce(float* __restrict__ dout, float* __restrict__ keepout, int writeKeep) {
    __shared__ unsigned s_vm[32], s_keep[32];
    int b   = blockIdx.x;
    int tid = threadIdx.x;      // 0..127
    int lane = tid & 31, wrp = tid >> 5;

    // vmask ballots: 8 iterations x 4 warps cover 32 words
    #pragma unroll
    for (int it = 0; it < 8; it++) {
        int row = it * 128 + tid;
        float scv = g_topsc[b * KTOP + row];
        unsigned bal = __ballot_sync(0xFFFFFFFFu, scv > 0.0f);
        if (lane == 0) s_vm[it * 4 + wrp] = bal;
    }
    __syncthreads();

    if (tid < 32) {
        int l = tid;
        unsigned removed = ~s_vm[l];
        const unsigned* gm = &g_mask[(size_t)b * 32 * KTOP];
        unsigned d = g_diag[(b * 32 + 0) * 32 + l];

        for (int bi = 0; bi < 32; bi++) {
            const uint4* mrow = (const uint4*)&gm[(size_t)l * KTOP + bi * 32];
            uint4 m0 = mrow[0], m1 = mrow[1], m2 = mrow[2], m3 = mrow[3];
            uint4 m4 = mrow[4], m5 = mrow[5], m6 = mrow[6], m7 = mrow[7];
            unsigned dn = (bi < 31) ? g_diag[(b * 32 + bi + 1) * 32 + l] : 0u;

            unsigned r = __shfl_sync(0xFFFFFFFFu, removed, bi);
            unsigned dk[32];
            #pragma unroll
            for (int k = 0; k < 32; k++) dk[k] = __shfl_sync(0xFFFFFFFFu, d, k);

            // serial greedy within block: 3-op branchless chain per row
            #pragma unroll
            for (int k = 0; k < 32; k++) {
                unsigned msk = ((r >> k) & 1u) - 1u;   // ~0 if row k kept
                r |= dk[k] & msk;
            }
            unsigned keepw = ~r;

            unsigned mv[32] = { m0.x, m0.y, m0.z, m0.w, m1.x, m1.y, m1.z, m1.w,
                                m2.x, m2.y, m2.z, m2.w, m3.x, m3.y, m3.z, m3.w,
                                m4.x, m4.y, m4.z, m4.w, m5.x, m5.y, m5.z, m5.w,
                                m6.x, m6.y, m6.z, m6.w, m7.x, m7.y, m7.z, m7.w };
            unsigned acc = 0;
            #pragma unroll
            for (int k = 0; k < 32; k++) {
                unsigned msk = 0u - ((keepw >> k) & 1u);
                acc |= mv[k] & msk;
            }
            removed |= acc;
            d = dn;
        }
        s_keep[l] = ~removed;
    }
    __syncthreads();

    // masked output: 128 threads cover 1024 rows
    #pragma unroll
    for (int it = 0; it < 8; it++) {
        int row = it * 128 + tid;
        unsigned keepbit = (s_keep[row >> 5] >> (row & 31)) & 1u;
        float* o = dout + ((size_t)b * KTOP + row) * 16;
        if (!keepbit) {
            float4 z = make_float4(0.f, 0.f, 0.f, 0.f);
            ((float4*)o)[0] = z; ((float4*)o)[1] = z;
            ((float4*)o)[2] = z; ((float4*)o)[3] = z;
        }
        if (writeKeep) keepout[b * KTOP + row] = keepbit ? 1.0f : 0.0f;
    }
}

// ---------------- launch ----------------
extern "C" void kernel_launch(void* const* d_in, const int* in_sizes, int n_in,
                              void* d_out, int out_size) {
    const float* pred = (const float*)d_in[0];
    float* out = (float*)d_out;
    const int DET = B_IMG * KTOP * 16;
    int writeKeep = (out_size >= DET + B_IMG * KTOP) ? 1 : 0;
    float* keepout = out + DET;

    static int attr_done = 0;
    if (!attr_done) {
        cudaFuncSetAttribute((const void*)k12_topk,
                             cudaFuncAttributeMaxDynamicSharedMemorySize, SM_TOTAL);
        attr_done = 1;
    }

    k12_topk<<<B_IMG, 1024, SM_TOTAL>>>(pred, out);
    k3_mask<<<dim3(17, B_IMG), 1024>>>();
    k4_reduce<<<B_IMG, 128>>>(out, keepout, writeKeep);
}

// round 5
// speedup vs baseline: 1.9262x; 1.0888x over previous
#include <cuda_runtime.h>
#include <cstdint>
#include <climits>

#define B_IMG   32
#define N_PRED  25200
#define KTOP    1024
#define NBINS   4096
#define NCAND   2048
#define CONF_T  0.25f
#define IOU_T   0.45f
#define NTRI    528   // 32*33/2 upper-triangle 32x32 word-blocks

typedef unsigned long long ull;

// ---------------- scratch (static device globals; no allocation) ----------------
__device__ float        g_scores[B_IMG * N_PRED];    // 3.2 MB
__device__ float4       g_boxes[B_IMG * KTOP];
__device__ float        g_topsc[B_IMG * KTOP];
__device__ unsigned int g_mask[B_IMG * 32 * KTOP];   // [b][word w][row i]
__device__ unsigned int g_diag[B_IMG * 32 * 32];     // [b][blk][lane]

__device__ __forceinline__ ull umin64(ull a, ull b) { return a < b ? a : b; }
__device__ __forceinline__ ull umax64(ull a, ull b) { return a > b ? a : b; }

// ================= K1: scores only (full-chip, HBM phase) =================
__global__ void __launch_bounds__(1024)
k1_score(const float* __restrict__ pred) {
    int b = blockIdx.y;
    int i = blockIdx.x * 1024 + threadIdx.x;
    if (i >= N_PRED) return;
    const float* p = pred + ((size_t)(b * N_PRED + i)) * 16;
    float obj = __ldg(p + 4);
    float cls = __ldg(p + 15);
    float sc  = __fmul_rn(cls, obj);
    bool valid = (obj > CONF_T) && (sc > CONF_T);
    g_scores[b * N_PRED + i] = valid ? sc : -1.0f;
}

// ================= K2: hist + select + compact + sort + gather (per-image CTA) =================
__global__ void __launch_bounds__(1024, 1)
k2_topk(const float* __restrict__ pred, float* __restrict__ dout) {
    __shared__ unsigned s_hist[NBINS];    // 16 KB
    __shared__ ull      s_cand[NCAND];    // 16 KB
    __shared__ int      s_part[32];
    __shared__ int      s_binB, s_cnt;

    int b   = blockIdx.x;
    int t   = threadIdx.x;
    int lane = t & 31, wid = t >> 5;

    #pragma unroll
    for (int r = t; r < NBINS; r += 1024) s_hist[r] = 0u;
    if (t == 0) { s_binB = 0; s_cnt = 0; }
    __syncthreads();

    // ---- histogram from g_scores (L2-resident), float4 loads ----
    const float4* gs4 = (const float4*)&g_scores[b * N_PRED];
    const int N4 = N_PRED / 4;             // 6300
    for (int i = t; i < N4; i += 1024) {
        float4 s = gs4[i];
        float sv[4] = { s.x, s.y, s.z, s.w };
        #pragma unroll
        for (int c = 0; c < 4; c++) {
            if (sv[c] > 0.0f) {
                unsigned bin = (__float_as_uint(sv[c]) - 0x3E800000u) >> 12;
                if (bin > NBINS - 1) bin = NBINS - 1;
                atomicAdd(&s_hist[bin], 1u);
            }
        }
    }
    __syncthreads();

    // ---- reversed scan (warp hierarchy) + threshold bin ----
    unsigned c0 = s_hist[NBINS - 1 - 4 * t];
    unsigned c1 = s_hist[NBINS - 1 - (4 * t + 1)];
    unsigned c2 = s_hist[NBINS - 1 - (4 * t + 2)];
    unsigned c3 = s_hist[NBINS - 1 - (4 * t + 3)];
    int v = (int)(c0 + c1 + c2 + c3);
    int x = v;
    #pragma unroll
    for (int off = 1; off < 32; off <<= 1) {
        int y = __shfl_up_sync(0xFFFFFFFFu, x, off);
        if (lane >= off) x += y;
    }
    if (lane == 31) s_part[wid] = x;
    __syncthreads();
    if (wid == 0) {
        int y = s_part[lane];
        #pragma unroll
        for (int off = 1; off < 32; off <<= 1) {
            int z = __shfl_up_sync(0xFFFFFFFFu, y, off);
            if (lane >= off) y += z;
        }
        s_part[lane] = y;
    }
    __syncthreads();
    int incl = x + (wid > 0 ? s_part[wid - 1] : 0);
    int excl = incl - v;
    if (incl >= KTOP && excl < KTOP) {
        int c = excl;
        unsigned cs[4] = { c0, c1, c2, c3 };
        int rstar = 4 * t + 3;
        #pragma unroll
        for (int q = 0; q < 4; q++) {
            c += (int)cs[q];
            if (c >= KTOP) { rstar = 4 * t + q; break; }
        }
        s_binB = (NBINS - 1) - rstar;
    }
    __syncthreads();
    int binB = s_binB;

    // ---- compact candidates (float4 loads) ----
    for (int i = t; i < N4; i += 1024) {
        float4 s = gs4[i];
        float sv[4] = { s.x, s.y, s.z, s.w };
        #pragma unroll
        for (int c = 0; c < 4; c++) {
            if (sv[c] > 0.0f) {
                unsigned bits = __float_as_uint(sv[c]);
                unsigned bin  = (bits - 0x3E800000u) >> 12;
                if (bin > NBINS - 1) bin = NBINS - 1;
                if ((int)bin >= binB) {
                    unsigned desc = ~(bits | 0x80000000u);
                    ull key = ((ull)desc << 32) | (unsigned)(i * 4 + c);
                    int pos = atomicAdd(&s_cnt, 1);
                    if (pos < NCAND) s_cand[pos] = key;
                }
            }
        }
    }
    __syncthreads();
    int cnt = s_cnt; if (cnt > NCAND) cnt = NCAND;
    const ull PAD = ((ull)0xBF800000u << 32);
    for (int i0 = t; i0 < NCAND; i0 += 1024)
        if (i0 >= cnt) s_cand[i0] = PAD;
    __syncthreads();

    // ---- bitonic sort: registers + shfl; smem only for 32<=j<=512 ----
    ull e0 = s_cand[t];
    ull e1 = s_cand[t + 1024];
    for (int k = 2; k <= NCAND; k <<= 1) {
        bool dir0 = ((t & k) == 0);
        bool dir1 = (((t + 1024) & k) == 0);
        for (int j = k >> 1; j > 0; j >>= 1) {
            if (j == 1024) {
                ull lo = umin64(e0, e1), hi = umax64(e0, e1);
                e0 = lo; e1 = hi;
            } else if (j >= 32) {
                s_cand[t] = e0; s_cand[t + 1024] = e1;
                __syncthreads();
                ull f0 = s_cand[t ^ j];
                ull f1 = s_cand[(t ^ j) + 1024];
                bool lower = ((t & j) == 0);
                e0 = (lower == dir0) ? umin64(e0, f0) : umax64(e0, f0);
                e1 = (lower == dir1) ? umin64(e1, f1) : umax64(e1, f1);
                __syncthreads();
            } else {
                ull f0 = __shfl_xor_sync(0xFFFFFFFFu, e0, j);
                ull f1 = __shfl_xor_sync(0xFFFFFFFFu, e1, j);
                bool lower = ((t & j) == 0);
                e0 = (lower == dir0) ? umin64(e0, f0) : umax64(e0, f0);
                e1 = (lower == dir1) ? umin64(e1, f1) : umax64(e1, f1);
            }
        }
    }

    // ---- gather top-1024 (thread t holds sorted element t in e0) ----
    unsigned idx  = (unsigned)(e0 & 0xFFFFFFFFu);
    unsigned mono = ~((unsigned)(e0 >> 32));
    unsigned sbits = (mono & 0x80000000u) ? (mono & 0x7FFFFFFFu) : ~mono;
    float sc = __uint_as_float(sbits);

    const float* pb = pred + (size_t)b * N_PRED * 16;
    const float4* p4 = (const float4*)(pb + (size_t)idx * 16);
    float4 v0 = p4[0];
    float4 v1 = p4[1];
    float4 v2 = p4[2];
    float4 v3 = p4[3];

    float hw = __fmul_rn(v0.z, 0.5f), hh = __fmul_rn(v0.w, 0.5f);
    float x1 = __fsub_rn(v0.x, hw), y1 = __fsub_rn(v0.y, hh);
    float x2 = __fadd_rn(v0.x, hw), y2 = __fadd_rn(v0.y, hh);

    float4* o4 = (float4*)(dout + (((size_t)(b * KTOP)) + t) * 16);
    o4[0] = make_float4(x1, y1, x2, y2);
    o4[1] = make_float4(sc, v1.y, v1.z, v1.w);
    o4[2] = v2;
    o4[3] = make_float4(v3.x, v3.y, v3.z, 0.0f);

    g_boxes[b * KTOP + t] = make_float4(x1, y1, x2, y2);
    g_topsc[b * KTOP + t] = sc;
}

// ================= K3: suppression bitmask, triangle-packed, FFMA screen =================
__global__ void __launch_bounds__(1024)
k3_mask() {
    __shared__ float4 sbox[KTOP];
    __shared__ float  staj[KTOP];   // 0.45 * area * (1 - 1e-5)
    int b = blockIdx.y;
    int t = threadIdx.x;

    float4 bx = g_boxes[b * KTOP + t];
    sbox[t] = bx;
    float area = __fmul_rn(__fsub_rn(bx.z, bx.x), __fsub_rn(bx.w, bx.y));
    staj[t] = 0.45f * area * 0.99999f;
    __syncthreads();

    int g = blockIdx.x * 32 + (t >> 5);
    if (g >= NTRI) return;

    // map g -> (rowblock r, wordblock w>=r)
    int u = NTRI - g;
    int n = (int)((__fsqrt_rn((float)(8 * u + 1)) - 1.0f) * 0.5f);
    while (n * (n + 1) / 2 < u) n++;
    while ((n - 1) * n / 2 >= u) n--;
    int r    = 32 - n;
    int base = NTRI - n * (n + 1) / 2;
    int w    = r + (g - base);

    int lane = t & 31;
    int i = r * 32 + lane;
    float4 bi = sbox[i];
    float  ai = __fmul_rn(__fsub_rn(bi.z, bi.x), __fsub_rn(bi.w, bi.y));
    float  tqi_lo = 0.45f * (__fadd_rn(ai, 1e-7f)) * 0.99999f;

    unsigned amb = 0;
    #pragma unroll
    for (int kk = 0; kk < 32; kk++) {
        int j = w * 32 + kk;
        float4 bj = sbox[j];
        float iw = fmaxf(__fsub_rn(fminf(bi.z, bj.z), fmaxf(bi.x, bj.x)), 0.0f);
        float ih = fmaxf(__fsub_rn(fminf(bi.w, bj.w), fmaxf(bi.y, bj.y)), 0.0f);
        float inter = __fmul_rn(iw, ih);
        // screen: 1.45*inter > 0.45*(ai+aj+eps), RHS shrunk by 1e-5 (superset of true cond)
        if (fmaf(inter, 1.45f, -tqi_lo) > staj[j]) amb |= 1u << kk;
    }
    if (w == r) amb &= (0xFFFFFFFEu << lane);   // strict upper triangle on diagonal

    // exact resolution (bit-exact vs reference's RN divide)
    unsigned sup = 0;
    while (amb) {
        int kk = __ffs(amb) - 1; amb &= amb - 1;
        int j = w * 32 + kk;
        float4 bj = sbox[j];
        float aj = __fmul_rn(__fsub_rn(bj.z, bj.x), __fsub_rn(bj.w, bj.y));
        float iw = fmaxf(__fsub_rn(fminf(bi.z, bj.z), fmaxf(bi.x, bj.x)), 0.0f);
        float ih = fmaxf(__fsub_rn(fminf(bi.w, bj.w), fmaxf(bi.y, bj.y)), 0.0f);
        float inter = __fmul_rn(iw, ih);
        float den = __fadd_rn(__fsub_rn(__fadd_rn(ai, aj), inter), 1e-7f);
        if (__fdiv_rn(inter, den) > IOU_T) sup |= 1u << kk;
    }
    g_mask[((size_t)b * 32 + w) * KTOP + i] = sup;
    if (w == r) g_diag[(b * 32 + r) * 32 + lane] = sup;
}

// ================= K4: serial greedy (warp 0 of 128-thread block) + masked output =================
__global__ void __launch_bounds__(128)
k4_reduce(float* __restrict__ dout, float* __restrict__ keepout, int writeKeep) {
    __shared__ unsigned s_vm[32], s_keep[32];
    int b   = blockIdx.x;
    int tid = threadIdx.x;      // 0..127
    int lane = tid & 31, wrp = tid >> 5;

    #pragma unroll
    for (int it = 0; it < 8; it++) {
        int row = it * 128 + tid;
        float scv = g_topsc[b * KTOP + row];
        unsigned bal = __ballot_sync(0xFFFFFFFFu, scv > 0.0f);
        if (lane == 0) s_vm[it * 4 + wrp] = bal;
    }
    __syncthreads();

    if (tid < 32) {
        int l = tid;
        unsigned removed = ~s_vm[l];
        const unsigned* gm = &g_mask[(size_t)b * 32 * KTOP];
        unsigned d = g_diag[(b * 32 + 0) * 32 + l];

        for (int bi = 0; bi < 32; bi++) {
            const uint4* mrow = (const uint4*)&gm[(size_t)l * KTOP + bi * 32];
            uint4 m0 = mrow[0], m1 = mrow[1], m2 = mrow[2], m3 = mrow[3];
            uint4 m4 = mrow[4], m5 = mrow[5], m6 = mrow[6], m7 = mrow[7];
            unsigned dn = (bi < 31) ? g_diag[(b * 32 + bi + 1) * 32 + l] : 0u;

            unsigned r = __shfl_sync(0xFFFFFFFFu, removed, bi);
            unsigned dk[32];
            #pragma unroll
            for (int k = 0; k < 32; k++) dk[k] = __shfl_sync(0xFFFFFFFFu, d, k);

            #pragma unroll
            for (int k = 0; k < 32; k++) {
                unsigned msk = ((r >> k) & 1u) - 1u;   // ~0 if row k kept
                r |= dk[k] & msk;
            }
            unsigned keepw = ~r;

            unsigned mv[32] = { m0.x, m0.y, m0.z, m0.w, m1.x, m1.y, m1.z, m1.w,
                                m2.x, m2.y, m2.z, m2.w, m3.x, m3.y, m3.z, m3.w,
                                m4.x, m4.y, m4.z, m4.w, m5.x, m5.y, m5.z, m5.w,
                                m6.x, m6.y, m6.z, m6.w, m7.x, m7.y, m7.z, m7.w };
            unsigned acc = 0;
            #pragma unroll
            for (int k = 0; k < 32; k++) {
                unsigned msk = 0u - ((keepw >> k) & 1u);
                acc |= mv[k] & msk;
            }
            removed |= acc;
            d = dn;
        }
        s_keep[l] = ~removed;
    }
    __syncthreads();

    #pragma unroll
    for (int it = 0; it < 8; it++) {
        int row = it * 128 + tid;
        unsigned keepbit = (s_keep[row >> 5] >> (row & 31)) & 1u;
        float* o = dout + ((size_t)b * KTOP + row) * 16;
        if (!keepbit) {
            float4 z = make_float4(0.f, 0.f, 0.f, 0.f);
            ((float4*)o)[0] = z; ((float4*)o)[1] = z;
            ((float4*)o)[2] = z; ((float4*)o)[3] = z;
        }
        if (writeKeep) keepout[b * KTOP + row] = keepbit ? 1.0f : 0.0f;
    }
}

// ---------------- launch ----------------
extern "C" void kernel_launch(void* const* d_in, const int* in_sizes, int n_in,
                              void* d_out, int out_size) {
    const float* pred = (const float*)d_in[0];
    float* out = (float*)d_out;
    const int DET = B_IMG * KTOP * 16;
    int writeKeep = (out_size >= DET + B_IMG * KTOP) ? 1 : 0;
    float* keepout = out + DET;

    k1_score<<<dim3(25, B_IMG), 1024>>>(pred);
    k2_topk<<<B_IMG, 1024>>>(pred, out);
    k3_mask<<<dim3(17, B_IMG), 1024>>>();
    k4_reduce<<<B_IMG, 128>>>(out, keepout, writeKeep);
}